// round 3
// baseline (speedup 1.0000x reference)
#include <cuda_runtime.h>
#include <math_constants.h>

#define T_SRC   4096
#define T_DST   4096
#define HID     128
#define NHEADS  8
#define KTOP    128
#define TDENSE  1024
#define NT      512
#define QT      8
#define NW      (NT / 32)
#define NTILES  (T_DST / QT)

// union region: s_buf[NT] floats (2048B)  OR  {hist[257] pad 1040, eq[128] 512, cnt[4] 16}
#define UN_BYTES 2048
#define DYN_BYTES ((QT*T_SRC + QT*HID + QT*KTOP + QT*KTOP) * 4 + UN_BYTES)

// Order-preserving float -> uint32 key.
__device__ __forceinline__ unsigned fkey(float f) {
    unsigned b = __float_as_uint(f);
    return b ^ ((b & 0x80000000u) ? 0xFFFFFFFFu : 0x80000000u);
}

__device__ __forceinline__ float block_max(float v, float* sred) {
    #pragma unroll
    for (int o = 16; o; o >>= 1) v = fmaxf(v, __shfl_xor_sync(0xFFFFFFFFu, v, o));
    if ((threadIdx.x & 31) == 0) sred[threadIdx.x >> 5] = v;
    __syncthreads();
    if (threadIdx.x < 32) {
        float x = (threadIdx.x < NW) ? sred[threadIdx.x] : -CUDART_INF_F;
        #pragma unroll
        for (int o = 8; o; o >>= 1) x = fmaxf(x, __shfl_xor_sync(0xFFFFFFFFu, x, o));
        if (threadIdx.x == 0) sred[0] = x;
    }
    __syncthreads();
    v = sred[0];
    __syncthreads();
    return v;
}

__device__ __forceinline__ float block_sum(float v, float* sred) {
    #pragma unroll
    for (int o = 16; o; o >>= 1) v += __shfl_xor_sync(0xFFFFFFFFu, v, o);
    if ((threadIdx.x & 31) == 0) sred[threadIdx.x >> 5] = v;
    __syncthreads();
    if (threadIdx.x < 32) {
        float x = (threadIdx.x < NW) ? sred[threadIdx.x] : 0.0f;
        #pragma unroll
        for (int o = 8; o; o >>= 1) x += __shfl_xor_sync(0xFFFFFFFFu, x, o);
        if (threadIdx.x == 0) sred[0] = x;
    }
    __syncthreads();
    v = sred[0];
    __syncthreads();
    return v;
}

__global__ __launch_bounds__(NT, 1)
void tree_attn_tiled8(const float* __restrict__ q,
                      const float* __restrict__ k,
                      const float* __restrict__ v,
                      float* __restrict__ out) {
    extern __shared__ char smem_raw[];
    float*    s_sc   = (float*)smem_raw;                 // [QT][T_SRC]
    float*    s_q    = s_sc + QT * T_SRC;                // [QT][HID]
    int*      s_idx  = (int*)(s_q + QT * HID);           // [QT][KTOP]
    float*    s_w    = (float*)(s_idx + QT * KTOP);      // [QT][KTOP]
    char*     s_un   = (char*)(s_w + QT * KTOP);         // union region
    float*    s_buf  = (float*)s_un;                     // [NT]
    unsigned* s_hist = (unsigned*)s_un;                  // [257]
    int*      s_eq   = (int*)(s_un + 1040);              // [128]
    unsigned* s_cnt  = (unsigned*)(s_un + 1040 + 512);   // [4]
    __shared__ float s_redf[NW];

    const int tile = (NTILES - 1) - blockIdx.x;  // longest rows first
    const int h    = blockIdx.y;
    const int tid  = threadIdx.x;
    const int qi0  = tile * QT;
    const int n_max = qi0 + QT;

    const float* kbase = k + (size_t)h * T_SRC * HID;
    const float* vbase = v + (size_t)h * T_SRC * HID;

    for (int d = tid; d < QT * HID; d += NT)
        s_q[d] = q[((size_t)h * T_DST + qi0) * HID + d];
    __syncthreads();

    // ---- scores for all QT queries ----
    float mx[QT];
    #pragma unroll
    for (int s = 0; s < QT; s++) mx[s] = -CUDART_INF_F;

    for (int j = tid; j < n_max; j += NT) {
        const float4* kr = (const float4*)(kbase + (size_t)j * HID);
        float acc[QT];
        #pragma unroll
        for (int s = 0; s < QT; s++) acc[s] = 0.0f;
        #pragma unroll 4
        for (int d4 = 0; d4 < HID / 4; d4++) {
            float4 kk = kr[d4];
            #pragma unroll
            for (int s = 0; s < QT; s++) {
                const float4 qq = *(const float4*)&s_q[s * HID + d4 * 4];
                acc[s] = fmaf(kk.x, qq.x, acc[s]);
                acc[s] = fmaf(kk.y, qq.y, acc[s]);
                acc[s] = fmaf(kk.z, qq.z, acc[s]);
                acc[s] = fmaf(kk.w, qq.w, acc[s]);
            }
        }
        #pragma unroll
        for (int s = 0; s < QT; s++) {
            bool ok = (j <= qi0 + s);
            s_sc[s * T_SRC + j] = ok ? acc[s] : -CUDART_INF_F;
            if (ok) mx[s] = fmaxf(mx[s], acc[s]);
        }
    }
    __syncthreads();

    float m[QT];
    #pragma unroll
    for (int s = 0; s < QT; s++) m[s] = block_max(mx[s], s_redf);

    float inv[QT];

    if (qi0 < TDENSE) {
        // ================= dense causal softmax =================
        float psum[QT];
        #pragma unroll
        for (int s = 0; s < QT; s++) psum[s] = 0.0f;
        for (int j = tid; j < n_max; j += NT) {
            #pragma unroll
            for (int s = 0; s < QT; s++) {
                float sc = s_sc[s * T_SRC + j];
                float e = (j <= qi0 + s) ? __expf(sc - m[s]) : 0.0f;
                s_sc[s * T_SRC + j] = e;
                psum[s] += e;
            }
        }
        #pragma unroll
        for (int s = 0; s < QT; s++) inv[s] = 1.0f / block_sum(psum[s], s_redf);

        const int d  = tid & (HID - 1);
        const int qr = tid >> 7;  // 0..3
        float acc[QT];
        #pragma unroll
        for (int s = 0; s < QT; s++) acc[s] = 0.0f;
        for (int j = qr; j < n_max; j += 4) {
            float vv = vbase[(size_t)j * HID + d];
            #pragma unroll
            for (int s = 0; s < QT; s++)
                acc[s] = fmaf(s_sc[s * T_SRC + j], vv, acc[s]);
        }
        #pragma unroll
        for (int s = 0; s < QT; s++) {
            s_buf[tid] = acc[s];
            __syncthreads();
            if (tid < HID)
                out[((size_t)h * T_DST + qi0 + s) * HID + tid] =
                    (s_buf[tid] + s_buf[tid + HID] + s_buf[tid + 2*HID] + s_buf[tid + 3*HID]) * inv[s];
            __syncthreads();
        }
    } else {
        // ================= sparse: exact top-128 via 4-level radix select =================
        const int bound = ((n_max + NT - 1) / NT) * NT;

        #pragma unroll 1
        for (int s = 0; s < QT; s++) {
            const float* sc = s_sc + s * T_SRC;
            unsigned prefix = 0, ngt = 0;

            #pragma unroll 1
            for (int level = 3; level >= 0; level--) {
                if (tid < 257) s_hist[tid] = 0u;
                __syncthreads();

                const unsigned shift = level * 8;
                const unsigned pmask = (level == 3) ? 0u : (0xFFFFFFFFu << (shift + 8));

                for (int j = tid; j < bound; j += NT) {
                    unsigned bin = 256u;
                    if (j < n_max) {
                        unsigned key = fkey(sc[j]);
                        if ((key & pmask) == prefix) bin = (key >> shift) & 0xFFu;
                    }
                    unsigned peers = __match_any_sync(0xFFFFFFFFu, bin);
                    if ((__ffs(peers) - 1) == (tid & 31))
                        atomicAdd(&s_hist[bin], (unsigned)__popc(peers));
                }
                __syncthreads();

                if (tid < 32) {
                    unsigned g = 0;
                    #pragma unroll
                    for (int b = 0; b < 8; b++) g += s_hist[tid * 8 + b];
                    unsigned run = g;
                    #pragma unroll
                    for (int o = 1; o < 32; o <<= 1) {
                        unsigned u = __shfl_down_sync(0xFFFFFFFFu, run, o);
                        if (tid + o < 32) run += u;
                    }
                    unsigned S = run - g;
                    if (ngt + run >= KTOP && ngt + S < KTOP) {
                        unsigned acc2 = ngt + S;
                        #pragma unroll 1
                        for (int b = 7; b >= 0; b--) {
                            unsigned c = s_hist[tid * 8 + b];
                            if (acc2 + c >= KTOP) {
                                s_cnt[0] = prefix | ((unsigned)(tid * 8 + b) << shift);
                                s_cnt[1] = acc2;
                                break;
                            }
                            acc2 += c;
                        }
                    }
                }
                __syncthreads();
                prefix = s_cnt[0];
                ngt = s_cnt[1];
                __syncthreads();
            }

            const unsigned t_key = prefix;

            if (tid == 0) { s_cnt[2] = 0u; s_cnt[3] = 0u; }
            __syncthreads();
            for (int j = tid; j < n_max; j += NT) {
                unsigned key = fkey(sc[j]);
                if (key > t_key) {
                    unsigned p = atomicAdd(&s_cnt[2], 1u);
                    s_idx[s * KTOP + p] = j;
                } else if (key == t_key) {
                    unsigned p = atomicAdd(&s_cnt[3], 1u);
                    if (p < KTOP) s_eq[p] = j;
                }
            }
            __syncthreads();
            const int neq = (int)s_cnt[3];
            const int need = KTOP - (int)ngt;

            if (need < neq && tid == 0) {
                int c = (neq < KTOP) ? neq : KTOP;
                for (int a = 0; a < need; a++) {
                    int mb = a;
                    for (int b = a + 1; b < c; b++)
                        if (s_eq[b] < s_eq[mb]) mb = b;
                    int t2 = s_eq[a]; s_eq[a] = s_eq[mb]; s_eq[mb] = t2;
                }
            }
            __syncthreads();
            for (int a = tid; a < need; a += NT) s_idx[s * KTOP + (int)ngt + a] = s_eq[a];
            __syncthreads();

            float e = 0.0f;
            if (tid < KTOP) {
                e = __expf(sc[s_idx[s * KTOP + tid]] - m[s]);
                s_w[s * KTOP + tid] = e;
            }
            float tot = block_sum(e, s_redf);
            inv[s] = 1.0f / tot;
        }

        // AV over gathered rows
        const int d  = tid & (HID - 1);
        const int qr = tid >> 7;
        float acc[QT];
        #pragma unroll
        for (int s = 0; s < QT; s++) acc[s] = 0.0f;
        for (int a = qr; a < KTOP; a += 4) {
            #pragma unroll
            for (int s = 0; s < QT; s++) {
                int j = s_idx[s * KTOP + a];
                acc[s] = fmaf(s_w[s * KTOP + a], vbase[(size_t)j * HID + d], acc[s]);
            }
        }
        #pragma unroll
        for (int s = 0; s < QT; s++) {
            s_buf[tid] = acc[s];
            __syncthreads();
            if (tid < HID)
                out[((size_t)h * T_DST + qi0 + s) * HID + tid] =
                    (s_buf[tid] + s_buf[tid + HID] + s_buf[tid + 2*HID] + s_buf[tid + 3*HID]) * inv[s];
            __syncthreads();
        }
    }
}

extern "C" void kernel_launch(void* const* d_in, const int* in_sizes, int n_in,
                              void* d_out, int out_size) {
    const float* q = (const float*)d_in[0];
    const float* k = (const float*)d_in[1];
    const float* v = (const float*)d_in[2];
    float* out = (float*)d_out;

    cudaFuncSetAttribute(tree_attn_tiled8,
                         cudaFuncAttributeMaxDynamicSharedMemorySize, DYN_BYTES);

    dim3 grid(NTILES, NHEADS);
    tree_attn_tiled8<<<grid, NT, DYN_BYTES>>>(q, k, v, out);
}

// round 4
// speedup vs baseline: 1.0331x; 1.0331x over previous
#include <cuda_runtime.h>
#include <math_constants.h>

#define T_SRC   4096
#define T_DST   4096
#define HID     128
#define NHEADS  8
#define KTOP    128
#define TDENSE  1024
#define NT      512
#define QT      8
#define NW      (NT / 32)
#define NTILES  (T_DST / QT)

// union region: s_buf[NT] floats (2048B)  OR  {hist[257] pad 1040, eq[128] 512, cnt[4] 16}
#define UN_BYTES 2048
#define DYN_BYTES ((QT*T_SRC + QT*HID + QT*KTOP + QT*KTOP) * 4 + UN_BYTES)

// Order-preserving float -> uint32 key.
__device__ __forceinline__ unsigned fkey(float f) {
    unsigned b = __float_as_uint(f);
    return b ^ ((b & 0x80000000u) ? 0xFFFFFFFFu : 0x80000000u);
}

// Packed dual-FMA: acc.lo += a.lo*b.lo ; acc.hi += a.hi*b.hi  (one SASS FFMA2)
__device__ __forceinline__ void ffma2(unsigned long long& acc,
                                      const unsigned long long a,
                                      const unsigned long long b) {
    asm("fma.rn.f32x2 %0, %1, %2, %0;" : "+l"(acc) : "l"(a), "l"(b));
}
__device__ __forceinline__ float hsum2(unsigned long long a) {
    return __uint_as_float((unsigned)a) + __uint_as_float((unsigned)(a >> 32));
}

__device__ __forceinline__ float block_max(float v, float* sred) {
    #pragma unroll
    for (int o = 16; o; o >>= 1) v = fmaxf(v, __shfl_xor_sync(0xFFFFFFFFu, v, o));
    if ((threadIdx.x & 31) == 0) sred[threadIdx.x >> 5] = v;
    __syncthreads();
    if (threadIdx.x < 32) {
        float x = (threadIdx.x < NW) ? sred[threadIdx.x] : -CUDART_INF_F;
        #pragma unroll
        for (int o = 8; o; o >>= 1) x = fmaxf(x, __shfl_xor_sync(0xFFFFFFFFu, x, o));
        if (threadIdx.x == 0) sred[0] = x;
    }
    __syncthreads();
    v = sred[0];
    __syncthreads();
    return v;
}

__device__ __forceinline__ float block_sum(float v, float* sred) {
    #pragma unroll
    for (int o = 16; o; o >>= 1) v += __shfl_xor_sync(0xFFFFFFFFu, v, o);
    if ((threadIdx.x & 31) == 0) sred[threadIdx.x >> 5] = v;
    __syncthreads();
    if (threadIdx.x < 32) {
        float x = (threadIdx.x < NW) ? sred[threadIdx.x] : 0.0f;
        #pragma unroll
        for (int o = 8; o; o >>= 1) x += __shfl_xor_sync(0xFFFFFFFFu, x, o);
        if (threadIdx.x == 0) sred[0] = x;
    }
    __syncthreads();
    v = sred[0];
    __syncthreads();
    return v;
}

__global__ __launch_bounds__(NT, 1)
void tree_attn_f32x2(const float* __restrict__ q,
                     const float* __restrict__ k,
                     const float* __restrict__ v,
                     float* __restrict__ out) {
    extern __shared__ char smem_raw[];
    float*    s_sc   = (float*)smem_raw;                 // [QT][T_SRC]
    float*    s_q    = s_sc + QT * T_SRC;                // [QT][HID]
    int*      s_idx  = (int*)(s_q + QT * HID);           // [QT][KTOP]
    float*    s_w    = (float*)(s_idx + QT * KTOP);      // [QT][KTOP]
    char*     s_un   = (char*)(s_w + QT * KTOP);         // union region
    float*    s_buf  = (float*)s_un;                     // [NT]
    unsigned* s_hist = (unsigned*)s_un;                  // [257]
    int*      s_eq   = (int*)(s_un + 1040);              // [128]
    unsigned* s_cnt  = (unsigned*)(s_un + 1040 + 512);   // [4]
    __shared__ float s_redf[NW];

    const int tile = (NTILES - 1) - blockIdx.x;  // longest rows first
    const int h    = blockIdx.y;
    const int tid  = threadIdx.x;
    const int qi0  = tile * QT;
    const int n_max = qi0 + QT;

    const float* kbase = k + (size_t)h * T_SRC * HID;
    const float* vbase = v + (size_t)h * T_SRC * HID;

    for (int d = tid; d < QT * HID; d += NT)
        s_q[d] = q[((size_t)h * T_DST + qi0) * HID + d];
    __syncthreads();

    // ---- scores: 2 K rows per thread, packed f32x2 FMAs, q LDS shared across rows ----
    float mx[QT];
    #pragma unroll
    for (int s = 0; s < QT; s++) mx[s] = -CUDART_INF_F;

    for (int j0 = 0; j0 < n_max; j0 += 2 * NT) {
        const int jA = j0 + tid;
        const int jB = jA + NT;
        const int jAc = (jA < n_max) ? jA : (n_max - 1);
        const int jBc = (jB < n_max) ? jB : (n_max - 1);
        const ulonglong2* krA = (const ulonglong2*)(kbase + (size_t)jAc * HID);
        const ulonglong2* krB = (const ulonglong2*)(kbase + (size_t)jBc * HID);

        unsigned long long accA[QT], accB[QT];
        #pragma unroll
        for (int s = 0; s < QT; s++) { accA[s] = 0ull; accB[s] = 0ull; }

        #pragma unroll 2
        for (int ch = 0; ch < 8; ch++) {           // 8 chunks of 16 floats
            ulonglong2 a0 = krA[ch * 4 + 0];
            ulonglong2 a1 = krA[ch * 4 + 1];
            ulonglong2 a2 = krA[ch * 4 + 2];
            ulonglong2 a3 = krA[ch * 4 + 3];
            ulonglong2 b0 = krB[ch * 4 + 0];
            ulonglong2 b1 = krB[ch * 4 + 1];
            ulonglong2 b2 = krB[ch * 4 + 2];
            ulonglong2 b3 = krB[ch * 4 + 3];
            #pragma unroll
            for (int s = 0; s < QT; s++) {
                const ulonglong2* qp = (const ulonglong2*)(s_q + s * HID + ch * 16);
                ulonglong2 q0 = qp[0];
                ulonglong2 q1 = qp[1];
                ulonglong2 q2 = qp[2];
                ulonglong2 q3 = qp[3];
                ffma2(accA[s], a0.x, q0.x); ffma2(accB[s], b0.x, q0.x);
                ffma2(accA[s], a0.y, q0.y); ffma2(accB[s], b0.y, q0.y);
                ffma2(accA[s], a1.x, q1.x); ffma2(accB[s], b1.x, q1.x);
                ffma2(accA[s], a1.y, q1.y); ffma2(accB[s], b1.y, q1.y);
                ffma2(accA[s], a2.x, q2.x); ffma2(accB[s], b2.x, q2.x);
                ffma2(accA[s], a2.y, q2.y); ffma2(accB[s], b2.y, q2.y);
                ffma2(accA[s], a3.x, q3.x); ffma2(accB[s], b3.x, q3.x);
                ffma2(accA[s], a3.y, q3.y); ffma2(accB[s], b3.y, q3.y);
            }
        }

        #pragma unroll
        for (int s = 0; s < QT; s++) {
            if (jA < n_max) {
                bool ok = (jA <= qi0 + s);
                float sc = ok ? hsum2(accA[s]) : -CUDART_INF_F;
                s_sc[s * T_SRC + jA] = sc;
                mx[s] = fmaxf(mx[s], sc);
            }
            if (jB < n_max) {
                bool ok = (jB <= qi0 + s);
                float sc = ok ? hsum2(accB[s]) : -CUDART_INF_F;
                s_sc[s * T_SRC + jB] = sc;
                mx[s] = fmaxf(mx[s], sc);
            }
        }
    }
    __syncthreads();

    float m[QT];
    #pragma unroll
    for (int s = 0; s < QT; s++) m[s] = block_max(mx[s], s_redf);

    float inv[QT];

    if (qi0 < TDENSE) {
        // ================= dense causal softmax =================
        float psum[QT];
        #pragma unroll
        for (int s = 0; s < QT; s++) psum[s] = 0.0f;
        for (int j = tid; j < n_max; j += NT) {
            #pragma unroll
            for (int s = 0; s < QT; s++) {
                float sc = s_sc[s * T_SRC + j];
                float e = (j <= qi0 + s) ? __expf(sc - m[s]) : 0.0f;
                s_sc[s * T_SRC + j] = e;
                psum[s] += e;
            }
        }
        #pragma unroll
        for (int s = 0; s < QT; s++) inv[s] = 1.0f / block_sum(psum[s], s_redf);

        const int d  = tid & (HID - 1);
        const int qr = tid >> 7;  // 0..3
        float acc[QT];
        #pragma unroll
        for (int s = 0; s < QT; s++) acc[s] = 0.0f;
        for (int j = qr; j < n_max; j += 4) {
            float vv = vbase[(size_t)j * HID + d];
            #pragma unroll
            for (int s = 0; s < QT; s++)
                acc[s] = fmaf(s_sc[s * T_SRC + j], vv, acc[s]);
        }
        #pragma unroll
        for (int s = 0; s < QT; s++) {
            s_buf[tid] = acc[s];
            __syncthreads();
            if (tid < HID)
                out[((size_t)h * T_DST + qi0 + s) * HID + tid] =
                    (s_buf[tid] + s_buf[tid + HID] + s_buf[tid + 2*HID] + s_buf[tid + 3*HID]) * inv[s];
            __syncthreads();
        }
    } else {
        // ================= sparse: exact top-128 via 4-level radix select =================
        const int bound = ((n_max + NT - 1) / NT) * NT;

        #pragma unroll 1
        for (int s = 0; s < QT; s++) {
            const float* sc = s_sc + s * T_SRC;
            unsigned prefix = 0, ngt = 0;

            #pragma unroll 1
            for (int level = 3; level >= 0; level--) {
                if (tid < 257) s_hist[tid] = 0u;
                __syncthreads();

                const unsigned shift = level * 8;
                const unsigned pmask = (level == 3) ? 0u : (0xFFFFFFFFu << (shift + 8));

                for (int j = tid; j < bound; j += NT) {
                    unsigned bin = 256u;
                    if (j < n_max) {
                        unsigned key = fkey(sc[j]);
                        if ((key & pmask) == prefix) bin = (key >> shift) & 0xFFu;
                    }
                    unsigned peers = __match_any_sync(0xFFFFFFFFu, bin);
                    if ((__ffs(peers) - 1) == (tid & 31))
                        atomicAdd(&s_hist[bin], (unsigned)__popc(peers));
                }
                __syncthreads();

                if (tid < 32) {
                    unsigned g = 0;
                    #pragma unroll
                    for (int b = 0; b < 8; b++) g += s_hist[tid * 8 + b];
                    unsigned run = g;
                    #pragma unroll
                    for (int o = 1; o < 32; o <<= 1) {
                        unsigned u = __shfl_down_sync(0xFFFFFFFFu, run, o);
                        if (tid + o < 32) run += u;
                    }
                    unsigned S = run - g;
                    if (ngt + run >= KTOP && ngt + S < KTOP) {
                        unsigned acc2 = ngt + S;
                        #pragma unroll 1
                        for (int b = 7; b >= 0; b--) {
                            unsigned c = s_hist[tid * 8 + b];
                            if (acc2 + c >= KTOP) {
                                s_cnt[0] = prefix | ((unsigned)(tid * 8 + b) << shift);
                                s_cnt[1] = acc2;
                                break;
                            }
                            acc2 += c;
                        }
                    }
                }
                __syncthreads();
                prefix = s_cnt[0];
                ngt = s_cnt[1];
                __syncthreads();
            }

            const unsigned t_key = prefix;

            if (tid == 0) { s_cnt[2] = 0u; s_cnt[3] = 0u; }
            __syncthreads();
            for (int j = tid; j < n_max; j += NT) {
                unsigned key = fkey(sc[j]);
                if (key > t_key) {
                    unsigned p = atomicAdd(&s_cnt[2], 1u);
                    s_idx[s * KTOP + p] = j;
                } else if (key == t_key) {
                    unsigned p = atomicAdd(&s_cnt[3], 1u);
                    if (p < KTOP) s_eq[p] = j;
                }
            }
            __syncthreads();
            const int neq = (int)s_cnt[3];
            const int need = KTOP - (int)ngt;

            if (need < neq && tid == 0) {
                int c = (neq < KTOP) ? neq : KTOP;
                for (int a = 0; a < need; a++) {
                    int mb = a;
                    for (int b = a + 1; b < c; b++)
                        if (s_eq[b] < s_eq[mb]) mb = b;
                    int t2 = s_eq[a]; s_eq[a] = s_eq[mb]; s_eq[mb] = t2;
                }
            }
            __syncthreads();
            for (int a = tid; a < need; a += NT) s_idx[s * KTOP + (int)ngt + a] = s_eq[a];
            __syncthreads();

            float e = 0.0f;
            if (tid < KTOP) {
                e = __expf(sc[s_idx[s * KTOP + tid]] - m[s]);
                s_w[s * KTOP + tid] = e;
            }
            float tot = block_sum(e, s_redf);
            inv[s] = 1.0f / tot;
        }

        // AV over gathered rows
        const int d  = tid & (HID - 1);
        const int qr = tid >> 7;
        float acc[QT];
        #pragma unroll
        for (int s = 0; s < QT; s++) acc[s] = 0.0f;
        for (int a = qr; a < KTOP; a += 4) {
            #pragma unroll
            for (int s = 0; s < QT; s++) {
                int j = s_idx[s * KTOP + a];
                acc[s] = fmaf(s_w[s * KTOP + a], vbase[(size_t)j * HID + d], acc[s]);
            }
        }
        #pragma unroll
        for (int s = 0; s < QT; s++) {
            s_buf[tid] = acc[s];
            __syncthreads();
            if (tid < HID)
                out[((size_t)h * T_DST + qi0 + s) * HID + tid] =
                    (s_buf[tid] + s_buf[tid + HID] + s_buf[tid + 2*HID] + s_buf[tid + 3*HID]) * inv[s];
            __syncthreads();
        }
    }
}

extern "C" void kernel_launch(void* const* d_in, const int* in_sizes, int n_in,
                              void* d_out, int out_size) {
    const float* q = (const float*)d_in[0];
    const float* k = (const float*)d_in[1];
    const float* v = (const float*)d_in[2];
    float* out = (float*)d_out;

    cudaFuncSetAttribute(tree_attn_f32x2,
                         cudaFuncAttributeMaxDynamicSharedMemorySize, DYN_BYTES);

    dim3 grid(NTILES, NHEADS);
    tree_attn_f32x2<<<grid, NT, DYN_BYTES>>>(q, k, v, out);
}

// round 5
// speedup vs baseline: 1.1461x; 1.1094x over previous
#include <cuda_runtime.h>
#include <math_constants.h>

#define T_SRC   4096
#define T_DST   4096
#define HID     128
#define NHEADS  8
#define KTOP    128
#define TDENSE  1024
#define NT      512
#define QT      8
#define NW      (NT / 32)
#define NTILES  (T_DST / QT)

#define HPAD      264      // padded 257-bin histogram row
#define CAND_CAP  1536
#define C2_CAP    256

// ---- dynamic smem layout (words) ----
#define W_SC    (QT * T_SRC)          // scores
#define W_Q     (QT * HID)
#define W_IDX   (QT * KTOP)
#define W_W     (QT * KTOP)
#define W_H3    (QT * HPAD)
#define W_CAND  (QT * CAND_CAP)
#define W_C2    (QT * C2_CAP)
#define W_EQ    KTOP
#define W_CTRL  64
#define W_SEL   (W_H3 + W_CAND + W_C2 + W_EQ + W_CTRL)
#define DYN_BYTES ((W_SC + W_Q + W_IDX + W_W + W_SEL) * 4)

// Order-preserving float -> uint32 key.
__device__ __forceinline__ unsigned fkey(float f) {
    unsigned b = __float_as_uint(f);
    return b ^ ((b & 0x80000000u) ? 0xFFFFFFFFu : 0x80000000u);
}

// Packed dual-FMA (one SASS FFMA2)
__device__ __forceinline__ void ffma2(unsigned long long& acc,
                                      const unsigned long long a,
                                      const unsigned long long b) {
    asm("fma.rn.f32x2 %0, %1, %2, %0;" : "+l"(acc) : "l"(a), "l"(b));
}
__device__ __forceinline__ float hsum2(unsigned long long a) {
    return __uint_as_float((unsigned)a) + __uint_as_float((unsigned)(a >> 32));
}

__device__ __forceinline__ float block_max(float v, float* sred) {
    #pragma unroll
    for (int o = 16; o; o >>= 1) v = fmaxf(v, __shfl_xor_sync(0xFFFFFFFFu, v, o));
    if ((threadIdx.x & 31) == 0) sred[threadIdx.x >> 5] = v;
    __syncthreads();
    if (threadIdx.x < 32) {
        float x = (threadIdx.x < NW) ? sred[threadIdx.x] : -CUDART_INF_F;
        #pragma unroll
        for (int o = 8; o; o >>= 1) x = fmaxf(x, __shfl_xor_sync(0xFFFFFFFFu, x, o));
        if (threadIdx.x == 0) sred[0] = x;
    }
    __syncthreads();
    v = sred[0];
    __syncthreads();
    return v;
}

__device__ __forceinline__ float block_sum(float v, float* sred) {
    #pragma unroll
    for (int o = 16; o; o >>= 1) v += __shfl_xor_sync(0xFFFFFFFFu, v, o);
    if ((threadIdx.x & 31) == 0) sred[threadIdx.x >> 5] = v;
    __syncthreads();
    if (threadIdx.x < 32) {
        float x = (threadIdx.x < NW) ? sred[threadIdx.x] : 0.0f;
        #pragma unroll
        for (int o = 8; o; o >>= 1) x += __shfl_xor_sync(0xFFFFFFFFu, x, o);
        if (threadIdx.x == 0) sred[0] = x;
    }
    __syncthreads();
    v = sred[0];
    __syncthreads();
    return v;
}

__global__ __launch_bounds__(NT, 1)
void tree_attn_r5(const float* __restrict__ q,
                  const float* __restrict__ k,
                  const float* __restrict__ v,
                  float* __restrict__ out) {
    extern __shared__ char smem_raw[];
    float*    s_sc   = (float*)smem_raw;                     // [QT][T_SRC]
    float*    s_q    = s_sc + W_SC;                          // [QT][HID]
    int*      s_idx  = (int*)(s_q + W_Q);                    // [QT][KTOP]
    float*    s_w    = (float*)(s_idx + W_IDX);              // [QT][KTOP]
    unsigned* s_h3   = (unsigned*)(s_w + W_W);               // [QT][HPAD]
    int*      s_cand = (int*)(s_h3 + W_H3);                  // [QT][CAND_CAP]
    int*      s_c2   = (int*)(s_cand + W_CAND);              // [QT][C2_CAP]
    int*      s_eq   = (int*)(s_c2 + W_C2);                  // [KTOP]
    unsigned* s_ctrl = (unsigned*)(s_eq + W_EQ);             // [W_CTRL]
    float*    s_buf  = (float*)s_h3;                         // [NT] union (dense phase)
    unsigned* s_b3   = s_ctrl;            // [8]
    unsigned* s_ngt3 = s_ctrl + 8;        // [8]
    unsigned* s_gtc  = s_ctrl + 16;       // [8]
    unsigned* s_cc   = s_ctrl + 24;       // [8]
    unsigned* s_ovf  = s_ctrl + 32;       // [8]
    unsigned* s_misc = s_ctrl + 40;       // [8]
    __shared__ float s_redf[NW];

    const int tile = (NTILES - 1) - blockIdx.x;  // longest rows first
    const int h    = blockIdx.y;
    const int tid  = threadIdx.x;
    const int wid  = tid >> 5;
    const int lane = tid & 31;
    const unsigned lmlt = (1u << lane) - 1u;
    const int qi0  = tile * QT;
    const int n_max = qi0 + QT;

    const float* kbase = k + (size_t)h * T_SRC * HID;
    const float* vbase = v + (size_t)h * T_SRC * HID;

    for (int d = tid; d < QT * HID; d += NT)
        s_q[d] = q[((size_t)h * T_DST + qi0) * HID + d];
    __syncthreads();

    // ---- scores: 2 K rows per thread, packed f32x2 FMAs ----
    float mx[QT];
    #pragma unroll
    for (int s = 0; s < QT; s++) mx[s] = -CUDART_INF_F;

    for (int j0 = 0; j0 < n_max; j0 += 2 * NT) {
        const int jA = j0 + tid;
        const int jB = jA + NT;
        const int jAc = (jA < n_max) ? jA : (n_max - 1);
        const int jBc = (jB < n_max) ? jB : (n_max - 1);
        const ulonglong2* krA = (const ulonglong2*)(kbase + (size_t)jAc * HID);
        const ulonglong2* krB = (const ulonglong2*)(kbase + (size_t)jBc * HID);

        unsigned long long accA[QT], accB[QT];
        #pragma unroll
        for (int s = 0; s < QT; s++) { accA[s] = 0ull; accB[s] = 0ull; }

        #pragma unroll 2
        for (int ch = 0; ch < 8; ch++) {
            ulonglong2 a0 = krA[ch * 4 + 0];
            ulonglong2 a1 = krA[ch * 4 + 1];
            ulonglong2 a2 = krA[ch * 4 + 2];
            ulonglong2 a3 = krA[ch * 4 + 3];
            ulonglong2 b0 = krB[ch * 4 + 0];
            ulonglong2 b1 = krB[ch * 4 + 1];
            ulonglong2 b2 = krB[ch * 4 + 2];
            ulonglong2 b3 = krB[ch * 4 + 3];
            #pragma unroll
            for (int s = 0; s < QT; s++) {
                const ulonglong2* qp = (const ulonglong2*)(s_q + s * HID + ch * 16);
                ulonglong2 q0 = qp[0];
                ulonglong2 q1 = qp[1];
                ulonglong2 q2 = qp[2];
                ulonglong2 q3 = qp[3];
                ffma2(accA[s], a0.x, q0.x); ffma2(accB[s], b0.x, q0.x);
                ffma2(accA[s], a0.y, q0.y); ffma2(accB[s], b0.y, q0.y);
                ffma2(accA[s], a1.x, q1.x); ffma2(accB[s], b1.x, q1.x);
                ffma2(accA[s], a1.y, q1.y); ffma2(accB[s], b1.y, q1.y);
                ffma2(accA[s], a2.x, q2.x); ffma2(accB[s], b2.x, q2.x);
                ffma2(accA[s], a2.y, q2.y); ffma2(accB[s], b2.y, q2.y);
                ffma2(accA[s], a3.x, q3.x); ffma2(accB[s], b3.x, q3.x);
                ffma2(accA[s], a3.y, q3.y); ffma2(accB[s], b3.y, q3.y);
            }
        }

        #pragma unroll
        for (int s = 0; s < QT; s++) {
            if (jA < n_max) {
                bool ok = (jA <= qi0 + s);
                float sc = ok ? hsum2(accA[s]) : -CUDART_INF_F;
                s_sc[s * T_SRC + jA] = sc;
                mx[s] = fmaxf(mx[s], sc);
            }
            if (jB < n_max) {
                bool ok = (jB <= qi0 + s);
                float sc = ok ? hsum2(accB[s]) : -CUDART_INF_F;
                s_sc[s * T_SRC + jB] = sc;
                mx[s] = fmaxf(mx[s], sc);
            }
        }
    }
    __syncthreads();

    float m[QT];
    #pragma unroll
    for (int s = 0; s < QT; s++) m[s] = block_max(mx[s], s_redf);

    float inv[QT];

    if (qi0 < TDENSE) {
        // ================= dense causal softmax =================
        float psum[QT];
        #pragma unroll
        for (int s = 0; s < QT; s++) psum[s] = 0.0f;
        for (int j = tid; j < n_max; j += NT) {
            #pragma unroll
            for (int s = 0; s < QT; s++) {
                float sc = s_sc[s * T_SRC + j];
                float e = (j <= qi0 + s) ? __expf(sc - m[s]) : 0.0f;
                s_sc[s * T_SRC + j] = e;
                psum[s] += e;
            }
        }
        #pragma unroll
        for (int s = 0; s < QT; s++) inv[s] = 1.0f / block_sum(psum[s], s_redf);

        const int d  = tid & (HID - 1);
        const int qr = tid >> 7;
        float acc[QT];
        #pragma unroll
        for (int s = 0; s < QT; s++) acc[s] = 0.0f;
        for (int j = qr; j < n_max; j += 4) {
            float vv = vbase[(size_t)j * HID + d];
            #pragma unroll
            for (int s = 0; s < QT; s++)
                acc[s] = fmaf(s_sc[s * T_SRC + j], vv, acc[s]);
        }
        #pragma unroll
        for (int s = 0; s < QT; s++) {
            s_buf[tid] = acc[s];
            __syncthreads();
            if (tid < HID)
                out[((size_t)h * T_DST + qi0 + s) * HID + tid] =
                    (s_buf[tid] + s_buf[tid + HID] + s_buf[tid + 2*HID] + s_buf[tid + 3*HID]) * inv[s];
            __syncthreads();
        }
    } else {
        // ================= sparse: exact top-128 =================
        const int bound = ((n_max + NT - 1) / NT) * NT;

        // init histograms + control
        for (int i = tid; i < QT * HPAD; i += NT) s_h3[i] = 0u;
        if (tid < 8) { s_gtc[tid] = 0u; s_cc[tid] = 0u; s_ovf[tid] = 0u; }
        __syncthreads();

        // ---- combined top-byte histogram sweep (all 8 queries) ----
        for (int j = tid; j < bound; j += NT) {
            #pragma unroll
            for (int s = 0; s < QT; s++) {
                unsigned bin = 256u;
                if (j < n_max) bin = fkey(s_sc[s * T_SRC + j]) >> 24;
                unsigned peers = __match_any_sync(0xFFFFFFFFu, bin);
                if ((__ffs(peers) - 1) == lane)
                    atomicAdd(&s_h3[s * HPAD + bin], (unsigned)__popc(peers));
            }
        }
        __syncthreads();

        // ---- per-warp bin scan: warp s chooses byte b3[s], ngt3[s] ----
        if (wid < QT) {
            const int s = wid;
            unsigned g = 0;
            #pragma unroll
            for (int b = 0; b < 8; b++) g += s_h3[s * HPAD + lane * 8 + b];
            unsigned run = g;
            #pragma unroll
            for (int o = 1; o < 32; o <<= 1) {
                unsigned u = __shfl_down_sync(0xFFFFFFFFu, run, o);
                if (lane + o < 32) run += u;
            }
            unsigned S = run - g;
            int found = (run >= KTOP && S < KTOP);
            unsigned bl = 0, acc2 = 0;
            if (found) {
                acc2 = S;
                #pragma unroll 1
                for (int b = 7; b >= 0; b--) {
                    unsigned c = s_h3[s * HPAD + lane * 8 + b];
                    if (acc2 + c >= KTOP) { bl = lane * 8 + b; break; }
                    acc2 += c;
                }
            }
            unsigned fmask = __ballot_sync(0xFFFFFFFFu, found);
            int flane = __ffs(fmask) - 1;
            bl   = __shfl_sync(0xFFFFFFFFu, bl, flane);
            acc2 = __shfl_sync(0xFFFFFFFFu, acc2, flane);
            if (lane == 0) { s_b3[s] = bl; s_ngt3[s] = acc2; }
        }
        __syncthreads();

        // ---- combined compact sweep: byte > b3 -> s_idx, byte == b3 -> cand ----
        for (int j = tid; j < bound; j += NT) {
            #pragma unroll
            for (int s = 0; s < QT; s++) {
                unsigned bin = 257u;
                if (j < n_max) bin = fkey(s_sc[s * T_SRC + j]) >> 24;
                const unsigned b3v = s_b3[s];
                bool gt = (bin > b3v) && (bin <= 255u);
                bool eq = (bin == b3v);
                unsigned mg = __ballot_sync(0xFFFFFFFFu, gt);
                unsigned me = __ballot_sync(0xFFFFFFFFu, eq);
                unsigned baseg = 0, basee = 0;
                if (mg && lane == (unsigned)(__ffs(mg) - 1))
                    baseg = atomicAdd(&s_gtc[s], (unsigned)__popc(mg));
                if (me && lane == (unsigned)(__ffs(me) - 1))
                    basee = atomicAdd(&s_cc[s], (unsigned)__popc(me));
                if (mg) {
                    baseg = __shfl_sync(0xFFFFFFFFu, baseg, __ffs(mg) - 1);
                    if (gt) s_idx[s * KTOP + baseg + __popc(mg & lmlt)] = j;
                }
                if (me) {
                    basee = __shfl_sync(0xFFFFFFFFu, basee, __ffs(me) - 1);
                    if (eq) {
                        unsigned p = basee + __popc(me & lmlt);
                        if (p < CAND_CAP) s_cand[s * CAND_CAP + p] = j;
                    }
                }
            }
        }
        __syncthreads();

        // ---- per-warp refinement: levels 2..0 on candidate lists ----
        if (wid < QT) {
            const int s = wid;
            const float* sc = s_sc + s * T_SRC;
            int nc = (int)s_cc[s];
            unsigned ngt = s_ngt3[s];
            bool ok = (nc <= CAND_CAP);
            int cur = 0;
            int* lists[2] = { s_cand + s * CAND_CAP, s_c2 + s * C2_CAP };
            const int caps[2] = { CAND_CAP, C2_CAP };

            #pragma unroll 1
            for (int lvl = 2; lvl >= 0 && ok; lvl--) {
                const int shift = lvl * 8;
                for (int b = lane; b < 257; b += 32) s_h3[s * HPAD + b] = 0u;
                __syncwarp();
                const int rb = (nc + 31) & ~31;
                for (int i = lane; i < rb; i += 32) {
                    unsigned bin = 256u;
                    if (i < nc) bin = (fkey(sc[lists[cur][i]]) >> shift) & 255u;
                    unsigned peers = __match_any_sync(0xFFFFFFFFu, bin);
                    if ((__ffs(peers) - 1) == lane)
                        s_h3[s * HPAD + bin] += (unsigned)__popc(peers);
                }
                __syncwarp();
                unsigned g = 0;
                #pragma unroll
                for (int b = 0; b < 8; b++) g += s_h3[s * HPAD + lane * 8 + b];
                unsigned run = g;
                #pragma unroll
                for (int o = 1; o < 32; o <<= 1) {
                    unsigned u = __shfl_down_sync(0xFFFFFFFFu, run, o);
                    if (lane + o < 32) run += u;
                }
                unsigned S = run - g;
                int found = (ngt + run >= KTOP && ngt + S < KTOP);
                unsigned bl = 0, acc2 = 0;
                if (found) {
                    acc2 = ngt + S;
                    #pragma unroll 1
                    for (int b = 7; b >= 0; b--) {
                        unsigned c = s_h3[s * HPAD + lane * 8 + b];
                        if (acc2 + c >= KTOP) { bl = lane * 8 + b; break; }
                        acc2 += c;
                    }
                }
                unsigned fmask = __ballot_sync(0xFFFFFFFFu, found);
                int flane = __ffs(fmask) - 1;
                bl = __shfl_sync(0xFFFFFFFFu, bl, flane);
                // partition
                const int dst = cur ^ 1;
                int* dl = lists[dst];
                const int dcap = caps[dst];
                unsigned wg = ngt, we = 0;
                for (int i = lane; i < rb; i += 32) {
                    unsigned bin = 256u; int j = 0;
                    if (i < nc) { j = lists[cur][i]; bin = (fkey(sc[j]) >> shift) & 255u; }
                    bool gt = (bin > bl) && (bin <= 255u);
                    bool eq = (bin == bl);
                    unsigned mg = __ballot_sync(0xFFFFFFFFu, gt);
                    unsigned me = __ballot_sync(0xFFFFFFFFu, eq);
                    if (gt) s_idx[s * KTOP + wg + __popc(mg & lmlt)] = j;
                    if (eq) {
                        unsigned p = we + __popc(me & lmlt);
                        if ((int)p < dcap) dl[p] = j;
                    }
                    wg += __popc(mg); we += __popc(me);
                }
                ngt = wg;
                nc = (int)we;
                cur = dst;
                if (nc > dcap) ok = false;
                __syncwarp();
            }
            if (ok) {
                // exact ties: pick `need` smallest indices by rank
                const int need = KTOP - (int)ngt;
                const int* tl = lists[cur];
                for (int i = lane; i < nc; i += 32) {
                    int ji = tl[i];
                    int rank = 0;
                    for (int m2 = 0; m2 < nc; m2++) rank += (tl[m2] < ji);
                    if (rank < need) s_idx[s * KTOP + (int)ngt + rank] = ji;
                }
            } else if (lane == 0) {
                s_ovf[s] = 1u;
            }
        }
        __syncthreads();

        // ---- rare fallback: full 4-level block-wide radix for overflowed s ----
        unsigned ovf_any = 0;
        #pragma unroll
        for (int s = 0; s < QT; s++) ovf_any |= s_ovf[s];
        if (ovf_any) {
            #pragma unroll 1
            for (int s = 0; s < QT; s++) {
                if (!s_ovf[s]) continue;
                const float* sc = s_sc + s * T_SRC;
                unsigned prefix = 0, ngt = 0;
                #pragma unroll 1
                for (int level = 3; level >= 0; level--) {
                    for (int b = tid; b < 257; b += NT) s_h3[b] = 0u;
                    __syncthreads();
                    const unsigned shift = level * 8;
                    const unsigned pmask = (level == 3) ? 0u : (0xFFFFFFFFu << (shift + 8));
                    for (int j = tid; j < bound; j += NT) {
                        unsigned bin = 256u;
                        if (j < n_max) {
                            unsigned key = fkey(sc[j]);
                            if ((key & pmask) == prefix) bin = (key >> shift) & 0xFFu;
                        }
                        unsigned peers = __match_any_sync(0xFFFFFFFFu, bin);
                        if ((__ffs(peers) - 1) == lane)
                            atomicAdd(&s_h3[bin], (unsigned)__popc(peers));
                    }
                    __syncthreads();
                    if (tid < 32) {
                        unsigned g = 0;
                        #pragma unroll
                        for (int b = 0; b < 8; b++) g += s_h3[tid * 8 + b];
                        unsigned run = g;
                        #pragma unroll
                        for (int o = 1; o < 32; o <<= 1) {
                            unsigned u = __shfl_down_sync(0xFFFFFFFFu, run, o);
                            if (tid + o < 32) run += u;
                        }
                        unsigned S = run - g;
                        if (ngt + run >= KTOP && ngt + S < KTOP) {
                            unsigned acc2 = ngt + S;
                            #pragma unroll 1
                            for (int b = 7; b >= 0; b--) {
                                unsigned c = s_h3[tid * 8 + b];
                                if (acc2 + c >= KTOP) {
                                    s_misc[0] = prefix | ((unsigned)(tid * 8 + b) << shift);
                                    s_misc[1] = acc2;
                                    break;
                                }
                                acc2 += c;
                            }
                        }
                    }
                    __syncthreads();
                    prefix = s_misc[0];
                    ngt = s_misc[1];
                    __syncthreads();
                }
                const unsigned t_key = prefix;
                if (tid == 0) { s_misc[2] = 0u; s_misc[3] = 0u; }
                __syncthreads();
                for (int j = tid; j < n_max; j += NT) {
                    unsigned key = fkey(sc[j]);
                    if (key > t_key) {
                        unsigned p = atomicAdd(&s_misc[2], 1u);
                        s_idx[s * KTOP + p] = j;
                    } else if (key == t_key) {
                        unsigned p = atomicAdd(&s_misc[3], 1u);
                        if (p < KTOP) s_eq[p] = j;
                    }
                }
                __syncthreads();
                const int neq = (int)s_misc[3];
                const int need = KTOP - (int)ngt;
                if (need < neq && tid == 0) {
                    int c = (neq < KTOP) ? neq : KTOP;
                    for (int a = 0; a < need; a++) {
                        int mb = a;
                        for (int b = a + 1; b < c; b++)
                            if (s_eq[b] < s_eq[mb]) mb = b;
                        int t2 = s_eq[a]; s_eq[a] = s_eq[mb]; s_eq[mb] = t2;
                    }
                }
                __syncthreads();
                for (int a = tid; a < need; a += NT) s_idx[s * KTOP + (int)ngt + a] = s_eq[a];
                __syncthreads();
            }
        }

        // ---- softmax weights over selected 128 per query ----
        #pragma unroll 1
        for (int s = 0; s < QT; s++) {
            float e = 0.0f;
            if (tid < KTOP) {
                e = __expf(s_sc[s * T_SRC + s_idx[s * KTOP + tid]] - m[s]);
                s_w[s * KTOP + tid] = e;
            }
            float tot = block_sum(e, s_redf);
            inv[s] = 1.0f / tot;
        }
        __syncthreads();

        // ---- AV over gathered rows ----
        const int d  = tid & (HID - 1);
        const int qr = tid >> 7;
        float acc[QT];
        #pragma unroll
        for (int s = 0; s < QT; s++) acc[s] = 0.0f;
        for (int a = qr; a < KTOP; a += 4) {
            #pragma unroll
            for (int s = 0; s < QT; s++) {
                int j = s_idx[s * KTOP + a];
                acc[s] = fmaf(s_w[s * KTOP + a], vbase[(size_t)j * HID + d], acc[s]);
            }
        }
        #pragma unroll
        for (int s = 0; s < QT; s++) {
            __syncthreads();
            s_buf[tid] = acc[s];
            __syncthreads();
            if (tid < HID)
                out[((size_t)h * T_DST + qi0 + s) * HID + tid] =
                    (s_buf[tid] + s_buf[tid + HID] + s_buf[tid + 2*HID] + s_buf[tid + 3*HID]) * inv[s];
        }
    }
}

extern "C" void kernel_launch(void* const* d_in, const int* in_sizes, int n_in,
                              void* d_out, int out_size) {
    const float* q = (const float*)d_in[0];
    const float* k = (const float*)d_in[1];
    const float* v = (const float*)d_in[2];
    float* out = (float*)d_out;

    cudaFuncSetAttribute(tree_attn_r5,
                         cudaFuncAttributeMaxDynamicSharedMemorySize, DYN_BYTES);

    dim3 grid(NTILES, NHEADS);
    tree_attn_r5<<<grid, NT, DYN_BYTES>>>(q, k, v, out);
}

// round 7
// speedup vs baseline: 1.1841x; 1.0332x over previous
#include <cuda_runtime.h>
#include <math_constants.h>

#define T_SRC   4096
#define T_DST   4096
#define HID     128
#define NHEADS  8
#define KTOP    128
#define TDENSE  1024
#define NT      768
#define QT      8
#define NW      (NT / 32)
#define NTILES  (T_DST / QT)

#define HPAD      264
#define CAND_CAP  1536
#define C2_CAP    256

#define W_SC    (QT * T_SRC)
#define W_Q     (QT * HID)
#define W_IDX   (QT * KTOP)
#define W_W     (QT * KTOP)
#define W_H3    (QT * HPAD)
#define W_CAND  (QT * CAND_CAP)
#define W_C2    (QT * C2_CAP)
#define W_EQ    KTOP
#define W_CTRL  64
#define W_SEL   (W_H3 + W_CAND + W_C2 + W_EQ + W_CTRL)
#define DYN_BYTES ((W_SC + W_Q + W_IDX + W_W + W_SEL) * 4)

__device__ __forceinline__ unsigned fkey(float f) {
    unsigned b = __float_as_uint(f);
    return b ^ ((b & 0x80000000u) ? 0xFFFFFFFFu : 0x80000000u);
}

__device__ __forceinline__ void ffma2(unsigned long long& acc,
                                      const unsigned long long a,
                                      const unsigned long long b) {
    asm("fma.rn.f32x2 %0, %1, %2, %0;" : "+l"(acc) : "l"(a), "l"(b));
}
__device__ __forceinline__ float hsum2(unsigned long long a) {
    return __uint_as_float((unsigned)a) + __uint_as_float((unsigned)(a >> 32));
}

__device__ __forceinline__ float block_max(float v, float* sred) {
    #pragma unroll
    for (int o = 16; o; o >>= 1) v = fmaxf(v, __shfl_xor_sync(0xFFFFFFFFu, v, o));
    if ((threadIdx.x & 31) == 0) sred[threadIdx.x >> 5] = v;
    __syncthreads();
    if (threadIdx.x < 32) {
        float x = (threadIdx.x < NW) ? sred[threadIdx.x] : -CUDART_INF_F;
        #pragma unroll
        for (int o = 16; o; o >>= 1) x = fmaxf(x, __shfl_xor_sync(0xFFFFFFFFu, x, o));
        if (threadIdx.x == 0) sred[0] = x;
    }
    __syncthreads();
    v = sred[0];
    __syncthreads();
    return v;
}

__device__ __forceinline__ float block_sum(float v, float* sred) {
    #pragma unroll
    for (int o = 16; o; o >>= 1) v += __shfl_xor_sync(0xFFFFFFFFu, v, o);
    if ((threadIdx.x & 31) == 0) sred[threadIdx.x >> 5] = v;
    __syncthreads();
    if (threadIdx.x < 32) {
        float x = (threadIdx.x < NW) ? sred[threadIdx.x] : 0.0f;
        #pragma unroll
        for (int o = 16; o; o >>= 1) x += __shfl_xor_sync(0xFFFFFFFFu, x, o);
        if (threadIdx.x == 0) sred[0] = x;
    }
    __syncthreads();
    v = sred[0];
    __syncthreads();
    return v;
}

__global__ __launch_bounds__(NT, 1)
void tree_attn_r6(const float* __restrict__ q,
                  const float* __restrict__ k,
                  const float* __restrict__ v,
                  float* __restrict__ out) {
    extern __shared__ char smem_raw[];
    float*    s_sc   = (float*)smem_raw;                     // [QT][T_SRC]
    float*    s_q    = s_sc + W_SC;                          // [QT][HID]
    int*      s_idx  = (int*)(s_q + W_Q);                    // [QT][KTOP]
    float*    s_w    = (float*)(s_idx + W_IDX);              // [QT][KTOP]
    unsigned* s_h3   = (unsigned*)(s_w + W_W);               // [QT][HPAD]
    int*      s_cand = (int*)(s_h3 + W_H3);                  // [QT][CAND_CAP]
    int*      s_c2   = (int*)(s_cand + W_CAND);              // [QT][C2_CAP]
    int*      s_eq   = (int*)(s_c2 + W_C2);                  // [KTOP]
    unsigned* s_ctrl = (unsigned*)(s_eq + W_EQ);             // [W_CTRL]
    float*    s_buf  = (float*)s_h3;                         // [NT] union (AV phases)
    unsigned* s_b3   = s_ctrl;            // [8]
    unsigned* s_ngt3 = s_ctrl + 8;        // [8]
    unsigned* s_gtc  = s_ctrl + 16;       // [8]
    unsigned* s_cc   = s_ctrl + 24;       // [8]
    unsigned* s_ovf  = s_ctrl + 32;       // [8]
    unsigned* s_misc = s_ctrl + 40;       // [8]
    float*    s_inv  = (float*)(s_ctrl + 48);  // [8]
    __shared__ float s_redf[NW];

    const int tile = (NTILES - 1) - blockIdx.x;  // longest rows first
    const int h    = blockIdx.y;
    const int tid  = threadIdx.x;
    const int wid  = tid >> 5;
    const int lane = tid & 31;
    const unsigned lmlt = (1u << lane) - 1u;
    const int qi0  = tile * QT;
    const int n_max = qi0 + QT;

    const float* kbase = k + (size_t)h * T_SRC * HID;
    const float* vbase = v + (size_t)h * T_SRC * HID;

    for (int d = tid; d < QT * HID; d += NT)
        s_q[d] = q[((size_t)h * T_DST + qi0) * HID + d];
    __syncthreads();

    // ---- scores: 1 K row per thread, packed f32x2 FMAs ----
    float mx[QT];
    #pragma unroll
    for (int s = 0; s < QT; s++) mx[s] = -CUDART_INF_F;

    for (int j0 = 0; j0 < n_max; j0 += NT) {
        const int jA  = j0 + tid;
        const int jAc = (jA < n_max) ? jA : (n_max - 1);
        const ulonglong2* kr = (const ulonglong2*)(kbase + (size_t)jAc * HID);

        unsigned long long acc[QT];
        #pragma unroll
        for (int s = 0; s < QT; s++) acc[s] = 0ull;

        #pragma unroll 2
        for (int ch = 0; ch < 8; ch++) {
            ulonglong2 a0 = kr[ch * 4 + 0];
            ulonglong2 a1 = kr[ch * 4 + 1];
            ulonglong2 a2 = kr[ch * 4 + 2];
            ulonglong2 a3 = kr[ch * 4 + 3];
            #pragma unroll
            for (int s = 0; s < QT; s++) {
                const ulonglong2* qp = (const ulonglong2*)(s_q + s * HID + ch * 16);
                ulonglong2 q0 = qp[0];
                ulonglong2 q1 = qp[1];
                ulonglong2 q2 = qp[2];
                ulonglong2 q3 = qp[3];
                ffma2(acc[s], a0.x, q0.x);
                ffma2(acc[s], a0.y, q0.y);
                ffma2(acc[s], a1.x, q1.x);
                ffma2(acc[s], a1.y, q1.y);
                ffma2(acc[s], a2.x, q2.x);
                ffma2(acc[s], a2.y, q2.y);
                ffma2(acc[s], a3.x, q3.x);
                ffma2(acc[s], a3.y, q3.y);
            }
        }

        if (jA < n_max) {
            #pragma unroll
            for (int s = 0; s < QT; s++) {
                bool ok = (jA <= qi0 + s);
                float sc = ok ? hsum2(acc[s]) : -CUDART_INF_F;
                s_sc[s * T_SRC + jA] = sc;
                mx[s] = fmaxf(mx[s], sc);
            }
        }
    }
    __syncthreads();

    float m[QT];
    #pragma unroll
    for (int s = 0; s < QT; s++) m[s] = block_max(mx[s], s_redf);

    if (qi0 < TDENSE) {
        // ================= dense causal softmax =================
        float psum[QT];
        #pragma unroll
        for (int s = 0; s < QT; s++) psum[s] = 0.0f;
        for (int j = tid; j < n_max; j += NT) {
            #pragma unroll
            for (int s = 0; s < QT; s++) {
                float sc = s_sc[s * T_SRC + j];
                float e = (j <= qi0 + s) ? __expf(sc - m[s]) : 0.0f;
                s_sc[s * T_SRC + j] = e;
                psum[s] += e;
            }
        }
        float inv[QT];
        #pragma unroll
        for (int s = 0; s < QT; s++) inv[s] = 1.0f / block_sum(psum[s], s_redf);

        const int d  = tid & (HID - 1);
        const int qr = tid >> 7;   // 0..5
        float acc[QT];
        #pragma unroll
        for (int s = 0; s < QT; s++) acc[s] = 0.0f;
        for (int j = qr; j < n_max; j += 6) {
            float vv = vbase[(size_t)j * HID + d];
            #pragma unroll
            for (int s = 0; s < QT; s++)
                acc[s] = fmaf(s_sc[s * T_SRC + j], vv, acc[s]);
        }
        #pragma unroll
        for (int s = 0; s < QT; s++) {
            s_buf[tid] = acc[s];
            __syncthreads();
            if (tid < HID) {
                float r = 0.0f;
                #pragma unroll
                for (int p = 0; p < 6; p++) r += s_buf[tid + p * HID];
                out[((size_t)h * T_DST + qi0 + s) * HID + tid] = r * inv[s];
            }
            __syncthreads();
        }
    } else {
        // ================= sparse: exact top-128 =================
        const int bound = ((n_max + NT - 1) / NT) * NT;

        for (int i = tid; i < QT * HPAD; i += NT) s_h3[i] = 0u;
        if (tid < 8) { s_gtc[tid] = 0u; s_cc[tid] = 0u; s_ovf[tid] = 0u; }
        __syncthreads();

        // ---- combined top-byte histogram sweep ----
        for (int j = tid; j < bound; j += NT) {
            #pragma unroll
            for (int s = 0; s < QT; s++) {
                unsigned bin = 256u;
                if (j < n_max) bin = fkey(s_sc[s * T_SRC + j]) >> 24;
                unsigned peers = __match_any_sync(0xFFFFFFFFu, bin);
                if ((__ffs(peers) - 1) == lane)
                    atomicAdd(&s_h3[s * HPAD + bin], (unsigned)__popc(peers));
            }
        }
        __syncthreads();

        // ---- per-warp bin scan (warps 0..7) ----
        if (wid < QT) {
            const int s = wid;
            unsigned g = 0;
            #pragma unroll
            for (int b = 0; b < 8; b++) g += s_h3[s * HPAD + lane * 8 + b];
            unsigned run = g;
            #pragma unroll
            for (int o = 1; o < 32; o <<= 1) {
                unsigned u = __shfl_down_sync(0xFFFFFFFFu, run, o);
                if (lane + o < 32) run += u;
            }
            unsigned S = run - g;
            int found = (run >= KTOP && S < KTOP);
            unsigned bl = 0, acc2 = 0;
            if (found) {
                acc2 = S;
                #pragma unroll 1
                for (int b = 7; b >= 0; b--) {
                    unsigned c = s_h3[s * HPAD + lane * 8 + b];
                    if (acc2 + c >= KTOP) { bl = lane * 8 + b; break; }
                    acc2 += c;
                }
            }
            unsigned fmask = __ballot_sync(0xFFFFFFFFu, found);
            int flane = __ffs(fmask) - 1;
            bl   = __shfl_sync(0xFFFFFFFFu, bl, flane);
            acc2 = __shfl_sync(0xFFFFFFFFu, acc2, flane);
            if (lane == 0) { s_b3[s] = bl; s_ngt3[s] = acc2; }
        }
        __syncthreads();

        // ---- combined compact sweep ----
        for (int j = tid; j < bound; j += NT) {
            #pragma unroll
            for (int s = 0; s < QT; s++) {
                unsigned bin = 257u;
                if (j < n_max) bin = fkey(s_sc[s * T_SRC + j]) >> 24;
                const unsigned b3v = s_b3[s];
                bool gt = (bin > b3v) && (bin <= 255u);
                bool eq = (bin == b3v);
                unsigned mg = __ballot_sync(0xFFFFFFFFu, gt);
                unsigned me = __ballot_sync(0xFFFFFFFFu, eq);
                unsigned baseg = 0, basee = 0;
                if (mg && lane == (unsigned)(__ffs(mg) - 1))
                    baseg = atomicAdd(&s_gtc[s], (unsigned)__popc(mg));
                if (me && lane == (unsigned)(__ffs(me) - 1))
                    basee = atomicAdd(&s_cc[s], (unsigned)__popc(me));
                if (mg) {
                    baseg = __shfl_sync(0xFFFFFFFFu, baseg, __ffs(mg) - 1);
                    if (gt) s_idx[s * KTOP + baseg + __popc(mg & lmlt)] = j;
                }
                if (me) {
                    basee = __shfl_sync(0xFFFFFFFFu, basee, __ffs(me) - 1);
                    if (eq) {
                        unsigned p = basee + __popc(me & lmlt);
                        if (p < CAND_CAP) s_cand[s * CAND_CAP + p] = j;
                    }
                }
            }
        }
        __syncthreads();

        // ---- per-warp refinement (warps 0..7) ----
        if (wid < QT) {
            const int s = wid;
            const float* sc = s_sc + s * T_SRC;
            int nc = (int)s_cc[s];
            unsigned ngt = s_ngt3[s];
            bool ok = (nc <= CAND_CAP);
            int cur = 0;
            int* lists[2] = { s_cand + s * CAND_CAP, s_c2 + s * C2_CAP };
            const int caps[2] = { CAND_CAP, C2_CAP };

            #pragma unroll 1
            for (int lvl = 2; lvl >= 0 && ok; lvl--) {
                const int shift = lvl * 8;
                for (int b = lane; b < 257; b += 32) s_h3[s * HPAD + b] = 0u;
                __syncwarp();
                const int rb = (nc + 31) & ~31;
                for (int i = lane; i < rb; i += 32) {
                    unsigned bin = 256u;
                    if (i < nc) bin = (fkey(sc[lists[cur][i]]) >> shift) & 255u;
                    unsigned peers = __match_any_sync(0xFFFFFFFFu, bin);
                    if ((__ffs(peers) - 1) == lane)
                        s_h3[s * HPAD + bin] += (unsigned)__popc(peers);
                }
                __syncwarp();
                unsigned g = 0;
                #pragma unroll
                for (int b = 0; b < 8; b++) g += s_h3[s * HPAD + lane * 8 + b];
                unsigned run = g;
                #pragma unroll
                for (int o = 1; o < 32; o <<= 1) {
                    unsigned u = __shfl_down_sync(0xFFFFFFFFu, run, o);
                    if (lane + o < 32) run += u;
                }
                unsigned S = run - g;
                int found = (ngt + run >= KTOP && ngt + S < KTOP);
                unsigned bl = 0;
                if (found) {
                    unsigned acc2 = ngt + S;
                    #pragma unroll 1
                    for (int b = 7; b >= 0; b--) {
                        unsigned c = s_h3[s * HPAD + lane * 8 + b];
                        if (acc2 + c >= KTOP) { bl = lane * 8 + b; break; }
                        acc2 += c;
                    }
                }
                unsigned fmask = __ballot_sync(0xFFFFFFFFu, found);
                int flane = __ffs(fmask) - 1;
                bl = __shfl_sync(0xFFFFFFFFu, bl, flane);
                const int dst = cur ^ 1;
                int* dl = lists[dst];
                const int dcap = caps[dst];
                unsigned wg = ngt, we = 0;
                for (int i = lane; i < rb; i += 32) {
                    unsigned bin = 256u; int j = 0;
                    if (i < nc) { j = lists[cur][i]; bin = (fkey(sc[j]) >> shift) & 255u; }
                    bool gt = (bin > bl) && (bin <= 255u);
                    bool eq = (bin == bl);
                    unsigned mg = __ballot_sync(0xFFFFFFFFu, gt);
                    unsigned me = __ballot_sync(0xFFFFFFFFu, eq);
                    if (gt) s_idx[s * KTOP + wg + __popc(mg & lmlt)] = j;
                    if (eq) {
                        unsigned p = we + __popc(me & lmlt);
                        if ((int)p < dcap) dl[p] = j;
                    }
                    wg += __popc(mg); we += __popc(me);
                }
                ngt = wg;
                nc = (int)we;
                cur = dst;
                if (nc > dcap) ok = false;
                __syncwarp();
            }
            if (ok) {
                const int need = KTOP - (int)ngt;
                const int* tl = lists[cur];
                for (int i = lane; i < nc; i += 32) {
                    int ji = tl[i];
                    int rank = 0;
                    for (int m2 = 0; m2 < nc; m2++) rank += (tl[m2] < ji);
                    if (rank < need) s_idx[s * KTOP + (int)ngt + rank] = ji;
                }
            } else if (lane == 0) {
                s_ovf[s] = 1u;
            }
        }
        __syncthreads();

        // ---- rare fallback: full 4-level radix ----
        unsigned ovf_any = 0;
        #pragma unroll
        for (int s = 0; s < QT; s++) ovf_any |= s_ovf[s];
        if (ovf_any) {
            #pragma unroll 1
            for (int s = 0; s < QT; s++) {
                if (!s_ovf[s]) continue;
                const float* sc = s_sc + s * T_SRC;
                unsigned prefix = 0, ngt = 0;
                #pragma unroll 1
                for (int level = 3; level >= 0; level--) {
                    for (int b = tid; b < 257; b += NT) s_h3[b] = 0u;
                    __syncthreads();
                    const unsigned shift = level * 8;
                    const unsigned pmask = (level == 3) ? 0u : (0xFFFFFFFFu << (shift + 8));
                    for (int j = tid; j < bound; j += NT) {
                        unsigned bin = 256u;
                        if (j < n_max) {
                            unsigned key = fkey(sc[j]);
                            if ((key & pmask) == prefix) bin = (key >> shift) & 0xFFu;
                        }
                        unsigned peers = __match_any_sync(0xFFFFFFFFu, bin);
                        if ((__ffs(peers) - 1) == lane)
                            atomicAdd(&s_h3[bin], (unsigned)__popc(peers));
                    }
                    __syncthreads();
                    if (tid < 32) {
                        unsigned g = 0;
                        #pragma unroll
                        for (int b = 0; b < 8; b++) g += s_h3[tid * 8 + b];
                        unsigned run = g;
                        #pragma unroll
                        for (int o = 1; o < 32; o <<= 1) {
                            unsigned u = __shfl_down_sync(0xFFFFFFFFu, run, o);
                            if (tid + o < 32) run += u;
                        }
                        unsigned S = run - g;
                        if (ngt + run >= KTOP && ngt + S < KTOP) {
                            unsigned acc2 = ngt + S;
                            #pragma unroll 1
                            for (int b = 7; b >= 0; b--) {
                                unsigned c = s_h3[tid * 8 + b];
                                if (acc2 + c >= KTOP) {
                                    s_misc[0] = prefix | ((unsigned)(tid * 8 + b) << shift);
                                    s_misc[1] = acc2;
                                    break;
                                }
                                acc2 += c;
                            }
                        }
                    }
                    __syncthreads();
                    prefix = s_misc[0];
                    ngt = s_misc[1];
                    __syncthreads();
                }
                const unsigned t_key = prefix;
                if (tid == 0) { s_misc[2] = 0u; s_misc[3] = 0u; }
                __syncthreads();
                for (int j = tid; j < n_max; j += NT) {
                    unsigned key = fkey(sc[j]);
                    if (key > t_key) {
                        unsigned p = atomicAdd(&s_misc[2], 1u);
                        s_idx[s * KTOP + p] = j;
                    } else if (key == t_key) {
                        unsigned p = atomicAdd(&s_misc[3], 1u);
                        if (p < KTOP) s_eq[p] = j;
                    }
                }
                __syncthreads();
                const int neq = (int)s_misc[3];
                const int need = KTOP - (int)ngt;
                if (need < neq && tid == 0) {
                    int c = (neq < KTOP) ? neq : KTOP;
                    for (int a = 0; a < need; a++) {
                        int mb = a;
                        for (int b = a + 1; b < c; b++)
                            if (s_eq[b] < s_eq[mb]) mb = b;
                        int t2 = s_eq[a]; s_eq[a] = s_eq[mb]; s_eq[mb] = t2;
                    }
                }
                __syncthreads();
                for (int a = tid; a < need; a += NT) s_idx[s * KTOP + (int)ngt + a] = s_eq[a];
                __syncthreads();
            }
        }

        // ---- per-warp softmax weights (warps 0..7, no block barriers) ----
        if (wid < QT) {
            const int s = wid;
            float psum = 0.0f;
            #pragma unroll
            for (int i = 0; i < KTOP / 32; i++) {
                int a = lane + i * 32;
                float e = __expf(s_sc[s * T_SRC + s_idx[s * KTOP + a]] - m[s]);
                s_w[s * KTOP + a] = e;
                psum += e;
            }
            #pragma unroll
            for (int o = 16; o; o >>= 1) psum += __shfl_xor_sync(0xFFFFFFFFu, psum, o);
            if (lane == 0) s_inv[s] = 1.0f / psum;
        }
        __syncthreads();

        // ---- AV over gathered rows ----
        const int d  = tid & (HID - 1);
        const int qr = tid >> 7;   // 0..5
        float acc[QT];
        #pragma unroll
        for (int s = 0; s < QT; s++) acc[s] = 0.0f;
        for (int a = qr; a < KTOP; a += 6) {
            #pragma unroll
            for (int s = 0; s < QT; s++) {
                int j = s_idx[s * KTOP + a];
                acc[s] = fmaf(s_w[s * KTOP + a], vbase[(size_t)j * HID + d], acc[s]);
            }
        }
        #pragma unroll
        for (int s = 0; s < QT; s++) {
            __syncthreads();
            s_buf[tid] = acc[s];
            __syncthreads();
            if (tid < HID) {
                float r = 0.0f;
                #pragma unroll
                for (int p = 0; p < 6; p++) r += s_buf[tid + p * HID];
                out[((size_t)h * T_DST + qi0 + s) * HID + tid] = r * s_inv[s];
            }
        }
    }
}

extern "C" void kernel_launch(void* const* d_in, const int* in_sizes, int n_in,
                              void* d_out, int out_size) {
    const float* q = (const float*)d_in[0];
    const float* k = (const float*)d_in[1];
    const float* v = (const float*)d_in[2];
    float* out = (float*)d_out;

    cudaFuncSetAttribute(tree_attn_r6,
                         cudaFuncAttributeMaxDynamicSharedMemorySize, DYN_BYTES);

    dim3 grid(NTILES, NHEADS);
    tree_attn_r6<<<grid, NT, DYN_BYTES>>>(q, k, v, out);
}